// round 6
// baseline (speedup 1.0000x reference)
#include <cuda_runtime.h>
#include <cuda_fp16.h>
#include <math.h>
#include <stdint.h>

// ---------------------------------------------------------------------------
// Problem constants
// ---------------------------------------------------------------------------
#define Bn    4096
#define DH    784
#define DHP   832                 // padded K (13 * 64)
#define DE    16
#define NSR   5
#define NTOT  (Bn * (1 + NSR))
#define NTILE 32
#define NBLK  (NTILE * (NTILE + 1) / 2)   // 528
#define NCH   13                  // K chunks of 64 halves
#define NSTG  4                   // pipeline stages

#define ALPHA 0.9296875
#define BETA  0.0703125

__device__ __constant__ const float A_C  = 1.576943f;
__device__ __constant__ const float PW   = 1.7901216f;
__device__ __constant__ const float EPSc = 1e-4f;

// smem layout (bytes)
#define SM_STG  0                 // 4 stages x (A 16KB + B 16KB) = 131072
#define SM_EA   131072            // 4096
#define SM_EB   135168            // 4096
#define SM_ROW  139264            // [4][128][5] f32 = 10240
#define SM_COL  149504            // [2][128][5] f32 = 5120
#define SM_NHI  154624
#define SM_NHJ  155136
#define SM_NLI  155648
#define SM_NLJ  156160
#define SM_MBF  156672            // full[4], 8B each
#define SM_MBE  156704            // empty[4]
#define SM_MBQ  156736            // E-tile barrier
#define SM_TOT  156800

// ---------------------------------------------------------------------------
// Device scratch
// ---------------------------------------------------------------------------
// chunk-major, pre-swizzled fp16 X: [chunk][row][64], group u at slot u^(row&7)
__device__ __align__(128) __half g_Xc[(size_t)NCH * Bn * 64];
__device__ __align__(128) __half g_Eh[(size_t)Bn * DE];
__device__ double g_Sh[Bn], g_Sl[Bn], g_Shh[Bn], g_Sll[Bn], g_Shl[Bn];
__device__ float  g_sqh[Bn];
__device__ float  g_sql[Bn];

// ---------------------------------------------------------------------------
// Helpers
// ---------------------------------------------------------------------------
__device__ __forceinline__ unsigned h2u(__half2 h) {
    union { __half2 h; unsigned u; } c;
    c.h = h;
    return c.u;
}
__device__ __forceinline__ uint32_t s2u(const void* p) {
    uint32_t a;
    asm("{ .reg .u64 t; cvta.to.shared.u64 t, %1; cvt.u32.u64 %0, t; }"
        : "=r"(a) : "l"(p));
    return a;
}
__device__ __forceinline__ float sqrt_fast(float x) {
    float y; asm("sqrt.approx.f32 %0, %1;" : "=f"(y) : "f"(x)); return y;
}
__device__ __forceinline__ void minit(uint32_t mb, uint32_t cnt) {
    asm volatile("mbarrier.init.shared.b64 [%0], %1;" :: "r"(mb), "r"(cnt) : "memory");
}
__device__ __forceinline__ void marrive(uint32_t mb) {
    asm volatile("mbarrier.arrive.shared.b64 _, [%0];" :: "r"(mb) : "memory");
}
__device__ __forceinline__ void mexpect(uint32_t mb, uint32_t tx) {
    asm volatile("mbarrier.arrive.expect_tx.shared.b64 _, [%0], %1;"
                 :: "r"(mb), "r"(tx) : "memory");
}
__device__ __forceinline__ void mwait(uint32_t mb, uint32_t par) {
    asm volatile(
        "{\n\t.reg .pred P;\n"
        "LW%=:\n\t"
        "mbarrier.try_wait.parity.acquire.cta.shared::cta.b64 P, [%0], %1, 0x989680;\n\t"
        "@!P bra LW%=;\n\t}"
        :: "r"(mb), "r"(par) : "memory");
}
__device__ __forceinline__ void bulk_g2s(uint32_t dst, const void* src,
                                         uint32_t bytes, uint32_t mb) {
    asm volatile(
        "cp.async.bulk.shared::cluster.global.mbarrier::complete_tx::bytes "
        "[%0], [%1], %2, [%3];"
        :: "r"(dst), "l"(src), "r"(bytes), "r"(mb) : "memory");
}
__device__ __forceinline__ void ldsm4(uint32_t* r, uint32_t addr) {
    asm volatile("ldmatrix.sync.aligned.m8n8.x4.shared.b16 {%0,%1,%2,%3}, [%4];"
                 : "=r"(r[0]), "=r"(r[1]), "=r"(r[2]), "=r"(r[3]) : "r"(addr));
}
__device__ __forceinline__ void mma16816(float* d, const uint32_t* a, const uint32_t* b) {
    asm volatile(
        "mma.sync.aligned.m16n8k16.row.col.f32.f16.f16.f32 "
        "{%0,%1,%2,%3}, {%4,%5,%6,%7}, {%8,%9}, {%0,%1,%2,%3};"
        : "+f"(d[0]), "+f"(d[1]), "+f"(d[2]), "+f"(d[3])
        : "r"(a[0]), "r"(a[1]), "r"(a[2]), "r"(a[3]), "r"(b[0]), "r"(b[1]));
}

// ---------------------------------------------------------------------------
// Kernel 0: fp16 conversion into chunk-major pre-swizzled layout + norms
// ---------------------------------------------------------------------------
__global__ void __launch_bounds__(128) prep_k(const float* __restrict__ X,
                                              const float* __restrict__ E) {
    int row = blockIdx.x;
    int t = threadIdx.x;
    float s = 0.f;
    if (t < 104) {
        int c = t >> 3, u = t & 7;
        int col = c * 64 + u * 8;
        float v[8];
        if (col + 8 <= DH) {
            float4 a = *(const float4*)(X + (size_t)row * DH + col);
            float4 b = *(const float4*)(X + (size_t)row * DH + col + 4);
            v[0] = a.x; v[1] = a.y; v[2] = a.z; v[3] = a.w;
            v[4] = b.x; v[5] = b.y; v[6] = b.z; v[7] = b.w;
        } else {
            #pragma unroll
            for (int q = 0; q < 8; q++)
                v[q] = (col + q < DH) ? X[(size_t)row * DH + col + q] : 0.f;
        }
        __half2 h01 = __floats2half2_rn(v[0], v[1]);
        __half2 h23 = __floats2half2_rn(v[2], v[3]);
        __half2 h45 = __floats2half2_rn(v[4], v[5]);
        __half2 h67 = __floats2half2_rn(v[6], v[7]);
        // norm from rounded values
        float2 f;
        f = __half22float2(h01); s = fmaf(f.x, f.x, fmaf(f.y, f.y, s));
        f = __half22float2(h23); s = fmaf(f.x, f.x, fmaf(f.y, f.y, s));
        f = __half22float2(h45); s = fmaf(f.x, f.x, fmaf(f.y, f.y, s));
        f = __half22float2(h67); s = fmaf(f.x, f.x, fmaf(f.y, f.y, s));
        uint4 pk;
        pk.x = h2u(h01); pk.y = h2u(h23);
        pk.z = h2u(h45); pk.w = h2u(h67);
        size_t dst = ((size_t)c * Bn + row) * 64 + (size_t)((u ^ (row & 7)) * 8);
        *(uint4*)(g_Xc + dst) = pk;
    }
    #pragma unroll
    for (int o = 16; o; o >>= 1) s += __shfl_xor_sync(0xffffffffu, s, o);
    __shared__ float ws[4];
    if ((t & 31) == 0) ws[t >> 5] = s;
    __syncthreads();
    if (t < 16) {
        g_Eh[(size_t)row * DE + t] = __float2half(E[(size_t)row * 32 + t]);
    }
    if (t == 0) {
        g_sqh[row] = ws[0] + ws[1] + ws[2] + ws[3];
        float sl = 0.f;
        #pragma unroll
        for (int k = 0; k < DE; k++) {
            float v = __half2float(__float2half(E[(size_t)row * 32 + k]));
            sl = fmaf(v, v, sl);
        }
        g_sql[row] = sl;
        g_Sh[row] = 0.0; g_Sl[row] = 0.0; g_Shh[row] = 0.0;
        g_Sll[row] = 0.0; g_Shl[row] = 0.0;
    }
}

// ---------------------------------------------------------------------------
// Kernel 1: HMMA pairwise-moment tiles, bulk-TMA pipelined (528 blocks)
// ---------------------------------------------------------------------------
__global__ void __launch_bounds__(256, 1) pair_k() {
    extern __shared__ __align__(128) char smem[];
    const uint32_t sb = s2u(smem);
    const int tid = threadIdx.x;
    const int lane = tid & 31, wid = tid >> 5;
    const int wr = wid >> 2, wc = wid & 3;

    // triangular tile decode
    int idx = blockIdx.x, bi = 0;
    while ((bi + 1) * (65 - (bi + 1)) / 2 <= idx) bi++;
    int bj = bi + (idx - bi * (65 - bi) / 2);
    const bool offdiag = (bi != bj);
    const int i0 = bi * 128, j0 = bj * 128;

    // barriers + initial TMA issues (thread 0)
    if (tid == 0) {
        #pragma unroll
        for (int s = 0; s < NSTG; s++) {
            minit(sb + SM_MBF + s * 8, 1);
            minit(sb + SM_MBE + s * 8, 8);
        }
        minit(sb + SM_MBQ, 1);
        asm volatile("fence.proxy.async.shared::cta;" ::: "memory");
        mexpect(sb + SM_MBQ, 8192);
        bulk_g2s(sb + SM_EA, g_Eh + (size_t)i0 * DE, 4096, sb + SM_MBQ);
        bulk_g2s(sb + SM_EB, g_Eh + (size_t)j0 * DE, 4096, sb + SM_MBQ);
        #pragma unroll
        for (int cc = 0; cc < 3; cc++) {
            uint32_t fb = sb + SM_MBF + cc * 8;
            mexpect(fb, 32768);
            bulk_g2s(sb + SM_STG + cc * 32768,
                     g_Xc + ((size_t)cc * Bn + i0) * 64, 16384, fb);
            bulk_g2s(sb + SM_STG + cc * 32768 + 16384,
                     g_Xc + ((size_t)cc * Bn + j0) * 64, 16384, fb);
        }
    }

    float* nhI = (float*)(smem + SM_NHI);
    float* nhJ = (float*)(smem + SM_NHJ);
    float* nlI = (float*)(smem + SM_NLI);
    float* nlJ = (float*)(smem + SM_NLJ);
    if (tid < 128) {
        nhI[tid] = g_sqh[i0 + tid];
        nlI[tid] = g_sql[i0 + tid];
    } else {
        int r = tid - 128;
        nhJ[r] = g_sqh[j0 + r];
        nlJ[r] = g_sql[j0 + r];
    }
    __syncthreads();

    // fragment address components
    const int rbaseA = wr * 64 + (lane & 15);
    const int duA    = lane >> 4;
    const int rmA    = rbaseA & 7;
    const int nbase  = wc * 32 + (lane & 7) + ((lane >> 4) << 3);
    const int duB    = (lane >> 3) & 1;
    const int rmB    = lane & 7;

    float acc[4][4][4];
    #pragma unroll
    for (int a = 0; a < 4; a++)
        #pragma unroll
        for (int b = 0; b < 4; b++)
            #pragma unroll
            for (int c = 0; c < 4; c++) acc[a][b][c] = 0.f;

    // ---------------- low-D (16) gram ----------------
    mwait(sb + SM_MBQ, 0);
    {
        uint32_t ea[4][4], eb[2][4];
        #pragma unroll
        for (int mi = 0; mi < 4; mi++) {
            int rE = rbaseA + mi * 16;
            ldsm4(ea[mi], sb + SM_EA + rE * 32 + (duA << 4));
        }
        #pragma unroll
        for (int nt = 0; nt < 2; nt++) {
            int nE = nbase + nt * 16;
            ldsm4(eb[nt], sb + SM_EB + nE * 32 + (duB << 4));
        }
        #pragma unroll
        for (int mi = 0; mi < 4; mi++)
            #pragma unroll
            for (int ni = 0; ni < 4; ni++)
                mma16816(acc[mi][ni], ea[mi], &eb[ni >> 1][(ni & 1) * 2]);
    }
    __half2 lhp[4][4][2];
    #pragma unroll
    for (int mi = 0; mi < 4; mi++) {
        int r0 = wr * 64 + mi * 16 + (lane >> 2), r1 = r0 + 8;
        float nl0 = nlI[r0], nl1 = nlI[r1];
        #pragma unroll
        for (int ni = 0; ni < 4; ni++) {
            int c0 = wc * 32 + ni * 8 + ((lane & 3) << 1), c1 = c0 + 1;
            float ol0 = nlJ[c0], ol1 = nlJ[c1];
            float l00 = sqrt_fast(fmaxf(fmaf(-2.f, acc[mi][ni][0], nl0 + ol0), 0.f));
            float l01 = sqrt_fast(fmaxf(fmaf(-2.f, acc[mi][ni][1], nl0 + ol1), 0.f));
            float l10 = sqrt_fast(fmaxf(fmaf(-2.f, acc[mi][ni][2], nl1 + ol0), 0.f));
            float l11 = sqrt_fast(fmaxf(fmaf(-2.f, acc[mi][ni][3], nl1 + ol1), 0.f));
            lhp[mi][ni][0] = __floats2half2_rn(l00, l01);
            lhp[mi][ni][1] = __floats2half2_rn(l10, l11);
            acc[mi][ni][0] = 0.f; acc[mi][ni][1] = 0.f;
            acc[mi][ni][2] = 0.f; acc[mi][ni][3] = 0.f;
        }
    }

    // ---------------- high-D mainloop: 13 chunks, 4-stage TMA ring ----------
    for (int c = 0; c < NCH; c++) {
        if (tid == 0) {
            int cc = c + 3;
            if (cc < NCH) {
                int s = cc & 3;
                if (cc >= NSTG) mwait(sb + SM_MBE + s * 8, ((cc >> 2) + 1) & 1);
                uint32_t fb = sb + SM_MBF + s * 8;
                mexpect(fb, 32768);
                bulk_g2s(sb + SM_STG + s * 32768,
                         g_Xc + ((size_t)cc * Bn + i0) * 64, 16384, fb);
                bulk_g2s(sb + SM_STG + s * 32768 + 16384,
                         g_Xc + ((size_t)cc * Bn + j0) * 64, 16384, fb);
            }
        }
        int s = c & 3;
        mwait(sb + SM_MBF + s * 8, (c >> 2) & 1);
        uint32_t bA = sb + SM_STG + s * 32768;
        uint32_t bB = bA + 16384;
        #pragma unroll
        for (int ks = 0; ks < 4; ks++) {
            uint32_t afr[4][4], bfr[2][4];
            #pragma unroll
            for (int mi = 0; mi < 4; mi++) {
                int row = rbaseA + mi * 16;
                ldsm4(afr[mi], bA + row * 128 + (((2 * ks + duA) ^ rmA) << 4));
            }
            #pragma unroll
            for (int nt = 0; nt < 2; nt++) {
                int nb = nbase + nt * 16;
                ldsm4(bfr[nt], bB + nb * 128 + (((2 * ks + duB) ^ rmB) << 4));
            }
            #pragma unroll
            for (int mi = 0; mi < 4; mi++)
                #pragma unroll
                for (int ni = 0; ni < 4; ni++)
                    mma16816(acc[mi][ni], afr[mi], &bfr[ni >> 1][(ni & 1) * 2]);
        }
        if (lane == 0) marrive(sb + SM_MBE + s * 8);
    }

    // ---------------- epilogue: distances + moments ----------------
    float* rowSm = (float*)(smem + SM_ROW);
    float* colSm = (float*)(smem + SM_COL);
    float cacc[4][2][5];
    #pragma unroll
    for (int ni = 0; ni < 4; ni++)
        #pragma unroll
        for (int q = 0; q < 2; q++)
            #pragma unroll
            for (int m = 0; m < 5; m++) cacc[ni][q][m] = 0.f;

    #pragma unroll
    for (int mi = 0; mi < 4; mi++) {
        int r0 = wr * 64 + mi * 16 + (lane >> 2), r1 = r0 + 8;
        float nh0 = nhI[r0], nh1 = nhI[r1];
        float rA[5] = {0.f, 0.f, 0.f, 0.f, 0.f};
        float rB[5] = {0.f, 0.f, 0.f, 0.f, 0.f};
        #pragma unroll
        for (int ni = 0; ni < 4; ni++) {
            int c0 = wc * 32 + ni * 8 + ((lane & 3) << 1), c1 = c0 + 1;
            float oh0 = nhJ[c0], oh1 = nhJ[c1];
            float h00 = sqrt_fast(fmaxf(fmaf(-2.f, acc[mi][ni][0], nh0 + oh0), 0.f));
            float h01 = sqrt_fast(fmaxf(fmaf(-2.f, acc[mi][ni][1], nh0 + oh1), 0.f));
            float h10 = sqrt_fast(fmaxf(fmaf(-2.f, acc[mi][ni][2], nh1 + oh0), 0.f));
            float h11 = sqrt_fast(fmaxf(fmaf(-2.f, acc[mi][ni][3], nh1 + oh1), 0.f));
            float2 lp0 = __half22float2(lhp[mi][ni][0]);
            float2 lp1 = __half22float2(lhp[mi][ni][1]);
            rA[0] += h00 + h01;
            rA[1] += lp0.x + lp0.y;
            rA[2] = fmaf(h00, h00, fmaf(h01, h01, rA[2]));
            rA[3] = fmaf(lp0.x, lp0.x, fmaf(lp0.y, lp0.y, rA[3]));
            rA[4] = fmaf(h00, lp0.x, fmaf(h01, lp0.y, rA[4]));
            rB[0] += h10 + h11;
            rB[1] += lp1.x + lp1.y;
            rB[2] = fmaf(h10, h10, fmaf(h11, h11, rB[2]));
            rB[3] = fmaf(lp1.x, lp1.x, fmaf(lp1.y, lp1.y, rB[3]));
            rB[4] = fmaf(h10, lp1.x, fmaf(h11, lp1.y, rB[4]));
            cacc[ni][0][0] += h00 + h10;
            cacc[ni][0][1] += lp0.x + lp1.x;
            cacc[ni][0][2] = fmaf(h00, h00, fmaf(h10, h10, cacc[ni][0][2]));
            cacc[ni][0][3] = fmaf(lp0.x, lp0.x, fmaf(lp1.x, lp1.x, cacc[ni][0][3]));
            cacc[ni][0][4] = fmaf(h00, lp0.x, fmaf(h10, lp1.x, cacc[ni][0][4]));
            cacc[ni][1][0] += h01 + h11;
            cacc[ni][1][1] += lp0.y + lp1.y;
            cacc[ni][1][2] = fmaf(h01, h01, fmaf(h11, h11, cacc[ni][1][2]));
            cacc[ni][1][3] = fmaf(lp0.y, lp0.y, fmaf(lp1.y, lp1.y, cacc[ni][1][3]));
            cacc[ni][1][4] = fmaf(h01, lp0.y, fmaf(h11, lp1.y, cacc[ni][1][4]));
        }
        #pragma unroll
        for (int m = 0; m < 5; m++) {
            rA[m] += __shfl_xor_sync(0xffffffffu, rA[m], 1);
            rA[m] += __shfl_xor_sync(0xffffffffu, rA[m], 2);
            rB[m] += __shfl_xor_sync(0xffffffffu, rB[m], 1);
            rB[m] += __shfl_xor_sync(0xffffffffu, rB[m], 2);
        }
        if ((lane & 3) == 0) {
            #pragma unroll
            for (int m = 0; m < 5; m++) {
                rowSm[(wc * 128 + r0) * 5 + m] = rA[m];
                rowSm[(wc * 128 + r1) * 5 + m] = rB[m];
            }
        }
    }
    #pragma unroll
    for (int ni = 0; ni < 4; ni++)
        #pragma unroll
        for (int q = 0; q < 2; q++)
            #pragma unroll
            for (int m = 0; m < 5; m++) {
                float v = cacc[ni][q][m];
                v += __shfl_xor_sync(0xffffffffu, v, 4);
                v += __shfl_xor_sync(0xffffffffu, v, 8);
                v += __shfl_xor_sync(0xffffffffu, v, 16);
                cacc[ni][q][m] = v;
            }
    if (lane < 4) {
        #pragma unroll
        for (int ni = 0; ni < 4; ni++) {
            int c0 = wc * 32 + ni * 8 + (lane << 1);
            #pragma unroll
            for (int m = 0; m < 5; m++) {
                colSm[(wr * 128 + c0) * 5 + m]     = cacc[ni][0][m];
                colSm[(wr * 128 + c0 + 1) * 5 + m] = cacc[ni][1][m];
            }
        }
    }
    __syncthreads();

    if (tid < 128) {
        int r = tid;
        float s0 = 0.f, s1 = 0.f, s2 = 0.f, s3 = 0.f, s4 = 0.f;
        #pragma unroll
        for (int w = 0; w < 4; w++) {
            const float* p = &rowSm[(w * 128 + r) * 5];
            s0 += p[0]; s1 += p[1]; s2 += p[2]; s3 += p[3]; s4 += p[4];
        }
        int gi = i0 + r;
        atomicAdd(&g_Sh[gi],  (double)s0);
        atomicAdd(&g_Sl[gi],  (double)s1);
        atomicAdd(&g_Shh[gi], (double)s2);
        atomicAdd(&g_Sll[gi], (double)s3);
        atomicAdd(&g_Shl[gi], (double)s4);
    } else if (offdiag) {
        int cjj = tid - 128;
        float s0 = 0.f, s1 = 0.f, s2 = 0.f, s3 = 0.f, s4 = 0.f;
        #pragma unroll
        for (int w = 0; w < 2; w++) {
            const float* p = &colSm[(w * 128 + cjj) * 5];
            s0 += p[0]; s1 += p[1]; s2 += p[2]; s3 += p[3]; s4 += p[4];
        }
        int gj = j0 + cjj;
        atomicAdd(&g_Sh[gj],  (double)s0);
        atomicAdd(&g_Sl[gj],  (double)s1);
        atomicAdd(&g_Shh[gj], (double)s2);
        atomicAdd(&g_Sll[gj], (double)s3);
        atomicAdd(&g_Shl[gj], (double)s4);
    }
}

// ---------------------------------------------------------------------------
// Kernel 2: fused tail — CE loss + correlations + final combine (1 block)
// ---------------------------------------------------------------------------
__global__ void __launch_bounds__(1024) tail_k(const float* __restrict__ E,
                                               const int* __restrict__ perm,
                                               float* __restrict__ out) {
    int t = threadIdx.x;
    // --- CE part ---
    float ce = 0.f;
    for (int idx = t; idx < NTOT; idx += 1024) {
        float s = 0.f;
        if (idx < Bn) {
            const float* p = E + (size_t)idx * 32;
            #pragma unroll
            for (int k = 0; k < DE; k++) { float d = p[k] - p[DE + k]; s = fmaf(d, d, s); }
            float d  = sqrtf(s);
            float pd = 1.f / (1.f + A_C * powf(d, PW));
            ce += -logf(fmaxf(pd, EPSc));
        } else {
            int j = idx - Bn;
            const float* pt = E + (size_t)(j / NSR) * 32;
            const float* pf = E + (size_t)(perm[j] / NSR) * 32 + DE;
            #pragma unroll
            for (int k = 0; k < DE; k++) { float d = pt[k] - pf[k]; s = fmaf(d, d, s); }
            float d  = sqrtf(s);
            float pd = 1.f / (1.f + A_C * powf(d, PW));
            ce += -logf(fmaxf(1.f - pd, EPSc));
        }
    }
    // --- corr part ---
    double corr = 0.0;
    const double invB = 1.0 / (double)Bn;
    for (int i = t; i < Bn; i += 1024) {
        double Sh = g_Sh[i], Sl = g_Sl[i];
        float num = (float)(g_Shl[i] - Sh * Sl * invB);
        float vh  = (float)fmax(g_Shh[i] - Sh * Sh * invB, 0.0);
        float vl  = (float)fmax(g_Sll[i] - Sl * Sl * invB, 0.0);
        corr += (double)(num * rsqrtf(fmaxf(vh, 1e-30f)) * rsqrtf(fmaxf(vl, 1e-30f)));
    }
    // --- reductions ---
    double dce = (double)ce;
    #pragma unroll
    for (int o = 16; o; o >>= 1) {
        dce  += __shfl_xor_sync(0xffffffffu, dce, o);
        corr += __shfl_xor_sync(0xffffffffu, corr, o);
    }
    __shared__ double rce[32], rco[32];
    if ((t & 31) == 0) { rce[t >> 5] = dce; rco[t >> 5] = corr; }
    __syncthreads();
    if (t == 0) {
        double sce = 0.0, sco = 0.0;
        #pragma unroll
        for (int w = 0; w < 32; w++) { sce += rce[w]; sco += rco[w]; }
        out[0] = (float)(ALPHA * (sce / (double)NTOT) - BETA * (sco / (double)Bn));
    }
}

// ---------------------------------------------------------------------------
extern "C" void kernel_launch(void* const* d_in, const int* in_sizes, int n_in,
                              void* d_out, int out_size) {
    (void)in_sizes; (void)n_in; (void)out_size;
    const float* E    = (const float*)d_in[0];
    const float* X    = (const float*)d_in[1];
    const int*   perm = (const int*)d_in[2];
    float* out = (float*)d_out;

    cudaFuncSetAttribute(pair_k, cudaFuncAttributeMaxDynamicSharedMemorySize, SM_TOT);

    prep_k<<<Bn, 128>>>(X, E);
    pair_k<<<NBLK, 256, SM_TOT>>>();
    tail_k<<<1, 1024>>>(E, perm, out);
}

// round 7
// speedup vs baseline: 3.2307x; 3.2307x over previous
#include <cuda_runtime.h>
#include <cuda_fp16.h>
#include <math.h>
#include <stdint.h>

// ---------------------------------------------------------------------------
// Problem constants
// ---------------------------------------------------------------------------
#define Bn    4096
#define DH    784
#define DE    16
#define NSR   5
#define NTOT  (Bn * (1 + NSR))
#define NTILE 32
#define NBLK  (NTILE * (NTILE + 1) / 2)   // 528
#define NCH   7                   // K chunks of 128 halves (896 padded)
#define NCEB  96                  // CE blocks appended to prep grid

#define ALPHA 0.9296875
#define BETA  0.0703125

__device__ __constant__ const float A_C  = 1.576943f;
__device__ __constant__ const float PW   = 1.7901216f;
__device__ __constant__ const float EPSc = 1e-4f;

// smem layout (bytes)
#define SM_STG  0                 // 3 stages x (A 32KB + B 32KB) = 196608
#define SM_EA   196608            // 4096
#define SM_EB   200704            // 4096
#define SM_ROW  204800            // [4][128][5] f32 = 10240
#define SM_COL  215040            // [2][128][5] f32 = 5120
#define SM_NHI  220160            // 512 each
#define SM_NHJ  220672
#define SM_NLI  221184
#define SM_NLJ  221696
#define SM_TOT  222208

// ---------------------------------------------------------------------------
// Device scratch
// ---------------------------------------------------------------------------
// chunk-major, pre-swizzled fp16 X: [chunk][row][128], 16B group u at slot u^(row&7)
__device__ __align__(128) __half g_Xc[(size_t)NCH * Bn * 128];
__device__ __align__(128) __half g_Eh[(size_t)Bn * DE];
__device__ double g_Sh[Bn], g_Sl[Bn], g_Shh[Bn], g_Sll[Bn], g_Shl[Bn];
__device__ float  g_sqh[Bn];
__device__ float  g_sql[Bn];
__device__ double g_cePart[NCEB];

// ---------------------------------------------------------------------------
// Helpers
// ---------------------------------------------------------------------------
__device__ __forceinline__ unsigned h2u(__half2 h) {
    union { __half2 h; unsigned u; } c;
    c.h = h;
    return c.u;
}
__device__ __forceinline__ uint32_t s2u(const void* p) {
    uint32_t a;
    asm("{ .reg .u64 t; cvta.to.shared.u64 t, %1; cvt.u32.u64 %0, t; }"
        : "=r"(a) : "l"(p));
    return a;
}
__device__ __forceinline__ float sqrt_fast(float x) {
    float y; asm("sqrt.approx.f32 %0, %1;" : "=f"(y) : "f"(x)); return y;
}
__device__ __forceinline__ void cpa16(uint32_t dst, const void* src) {
    asm volatile("cp.async.cg.shared.global [%0], [%1], 16;"
                 :: "r"(dst), "l"(src) : "memory");
}
__device__ __forceinline__ void ldsm4(uint32_t* r, uint32_t addr) {
    asm volatile("ldmatrix.sync.aligned.m8n8.x4.shared.b16 {%0,%1,%2,%3}, [%4];"
                 : "=r"(r[0]), "=r"(r[1]), "=r"(r[2]), "=r"(r[3]) : "r"(addr));
}
__device__ __forceinline__ void mma16816(float* d, const uint32_t* a, const uint32_t* b) {
    asm volatile(
        "mma.sync.aligned.m16n8k16.row.col.f32.f16.f16.f32 "
        "{%0,%1,%2,%3}, {%4,%5,%6,%7}, {%8,%9}, {%0,%1,%2,%3};"
        : "+f"(d[0]), "+f"(d[1]), "+f"(d[2]), "+f"(d[3])
        : "r"(a[0]), "r"(a[1]), "r"(a[2]), "r"(a[3]), "r"(b[0]), "r"(b[1]));
}

// ---------------------------------------------------------------------------
// Kernel 0: fp16 conversion (chunk-major, pre-swizzled) + norms + CE blocks
// ---------------------------------------------------------------------------
__global__ void __launch_bounds__(128) prep_k(const float* __restrict__ X,
                                              const float* __restrict__ E,
                                              const int* __restrict__ perm) {
    int b = blockIdx.x;
    int t = threadIdx.x;

    if (b < Bn) {
        int row = b;
        float s = 0.f;
        if (t < 112) {
            int c = t >> 4, u = t & 15;
            int col = c * 128 + u * 8;
            float v[8];
            if (col < DH) {
                float4 a = *(const float4*)(X + (size_t)row * DH + col);
                float4 bq = *(const float4*)(X + (size_t)row * DH + col + 4);
                v[0] = a.x; v[1] = a.y; v[2] = a.z; v[3] = a.w;
                v[4] = bq.x; v[5] = bq.y; v[6] = bq.z; v[7] = bq.w;
            } else {
                #pragma unroll
                for (int q = 0; q < 8; q++) v[q] = 0.f;
            }
            __half2 h01 = __floats2half2_rn(v[0], v[1]);
            __half2 h23 = __floats2half2_rn(v[2], v[3]);
            __half2 h45 = __floats2half2_rn(v[4], v[5]);
            __half2 h67 = __floats2half2_rn(v[6], v[7]);
            float2 f;
            f = __half22float2(h01); s = fmaf(f.x, f.x, fmaf(f.y, f.y, s));
            f = __half22float2(h23); s = fmaf(f.x, f.x, fmaf(f.y, f.y, s));
            f = __half22float2(h45); s = fmaf(f.x, f.x, fmaf(f.y, f.y, s));
            f = __half22float2(h67); s = fmaf(f.x, f.x, fmaf(f.y, f.y, s));
            uint4 pk;
            pk.x = h2u(h01); pk.y = h2u(h23);
            pk.z = h2u(h45); pk.w = h2u(h67);
            size_t dst = ((size_t)c * Bn + row) * 128 + (size_t)((u ^ (row & 7)) * 8);
            *(uint4*)(g_Xc + dst) = pk;
        }
        #pragma unroll
        for (int o = 16; o; o >>= 1) s += __shfl_xor_sync(0xffffffffu, s, o);
        __shared__ float ws[4];
        if ((t & 31) == 0) ws[t >> 5] = s;
        __syncthreads();
        if (t < 16) {
            g_Eh[(size_t)row * DE + t] = __float2half(E[(size_t)row * 32 + t]);
        }
        if (t == 0) {
            g_sqh[row] = ws[0] + ws[1] + ws[2] + ws[3];
            float sl = 0.f;
            #pragma unroll
            for (int k = 0; k < DE; k++) {
                float v = __half2float(__float2half(E[(size_t)row * 32 + k]));
                sl = fmaf(v, v, sl);
            }
            g_sql[row] = sl;
            g_Sh[row] = 0.0; g_Sl[row] = 0.0; g_Shh[row] = 0.0;
            g_Sll[row] = 0.0; g_Shl[row] = 0.0;
        }
    } else {
        // CE blocks: 96 blocks x 128 threads x 2 items = 24576
        int ceb = b - Bn;
        float ce = 0.f;
        #pragma unroll
        for (int rep = 0; rep < 2; rep++) {
            int idx = ceb * 256 + rep * 128 + t;
            float sq = 0.f;
            if (idx < Bn) {
                const float* p = E + (size_t)idx * 32;
                #pragma unroll
                for (int k = 0; k < DE; k++) { float d = p[k] - p[DE + k]; sq = fmaf(d, d, sq); }
                float d  = sqrtf(sq);
                float pd = 1.f / (1.f + A_C * powf(d, PW));
                ce += -logf(fmaxf(pd, EPSc));
            } else {
                int j = idx - Bn;
                const float* pt = E + (size_t)(j / NSR) * 32;
                const float* pf = E + (size_t)(perm[j] / NSR) * 32 + DE;
                #pragma unroll
                for (int k = 0; k < DE; k++) { float d = pt[k] - pf[k]; sq = fmaf(d, d, sq); }
                float d  = sqrtf(sq);
                float pd = 1.f / (1.f + A_C * powf(d, PW));
                ce += -logf(fmaxf(1.f - pd, EPSc));
            }
        }
        #pragma unroll
        for (int o = 16; o; o >>= 1) ce += __shfl_xor_sync(0xffffffffu, ce, o);
        __shared__ float cw[4];
        if ((t & 31) == 0) cw[t >> 5] = ce;
        __syncthreads();
        if (t == 0)
            g_cePart[ceb] = (double)(cw[0] + cw[1] + cw[2] + cw[3]);
    }
}

// ---------------------------------------------------------------------------
// Kernel 1: HMMA pairwise-moment tiles (triangular, 528 blocks, 256 threads)
// 3-stage cp.async ring, one __syncthreads per chunk.
// ---------------------------------------------------------------------------
__global__ void __launch_bounds__(256, 1) pair_k() {
    extern __shared__ __align__(128) char smem[];
    const uint32_t sb = s2u(smem);
    const int tid = threadIdx.x;
    const int lane = tid & 31, wid = tid >> 5;
    const int wr = wid >> 2, wc = wid & 3;

    // triangular tile decode
    int idx = blockIdx.x, bi = 0;
    while ((bi + 1) * (65 - (bi + 1)) / 2 <= idx) bi++;
    int bj = bi + (idx - bi * (65 - bi) / 2);
    const bool offdiag = (bi != bj);
    const int i0 = bi * 128, j0 = bj * 128;

    float* nhI = (float*)(smem + SM_NHI);
    float* nhJ = (float*)(smem + SM_NHJ);
    float* nlI = (float*)(smem + SM_NLI);
    float* nlJ = (float*)(smem + SM_NLJ);
    if (tid < 128) {
        nhI[tid] = g_sqh[i0 + tid];
        nlI[tid] = g_sql[i0 + tid];
    } else {
        int r = tid - 128;
        nhJ[r] = g_sqh[j0 + r];
        nlJ[r] = g_sql[j0 + r];
    }

    // prologue: E tiles + chunk0 (group 0), chunk1 (group 1)
    cpa16(sb + SM_EA + tid * 16, g_Eh + (size_t)i0 * DE + tid * 8);
    cpa16(sb + SM_EB + tid * 16, g_Eh + (size_t)j0 * DE + tid * 8);
    {
        const __half* pA = g_Xc + ((size_t)0 * Bn + i0) * 128;
        const __half* pB = g_Xc + ((size_t)0 * Bn + j0) * 128;
        uint32_t dA = sb + SM_STG, dB = dA + 32768;
        #pragma unroll
        for (int p = 0; p < 8; p++) {
            int id = tid + p * 256;
            cpa16(dA + id * 16, pA + (size_t)id * 8);
            cpa16(dB + id * 16, pB + (size_t)id * 8);
        }
    }
    asm volatile("cp.async.commit_group;" ::: "memory");
    {
        const __half* pA = g_Xc + ((size_t)1 * Bn + i0) * 128;
        const __half* pB = g_Xc + ((size_t)1 * Bn + j0) * 128;
        uint32_t dA = sb + SM_STG + 65536, dB = dA + 32768;
        #pragma unroll
        for (int p = 0; p < 8; p++) {
            int id = tid + p * 256;
            cpa16(dA + id * 16, pA + (size_t)id * 8);
            cpa16(dB + id * 16, pB + (size_t)id * 8);
        }
    }
    asm volatile("cp.async.commit_group;" ::: "memory");
    asm volatile("cp.async.wait_group 1;" ::: "memory");   // E + chunk0 done
    __syncthreads();

    // fragment address components
    const int rbaseA = wr * 64 + (lane & 15);
    const int duA    = lane >> 4;
    const int rmA    = rbaseA & 7;
    const int nbase  = wc * 32 + (lane & 7) + ((lane >> 4) << 3);
    const int duB    = (lane >> 3) & 1;
    const int rmB    = lane & 7;

    float acc[4][4][4];
    #pragma unroll
    for (int a = 0; a < 4; a++)
        #pragma unroll
        for (int b = 0; b < 4; b++)
            #pragma unroll
            for (int c = 0; c < 4; c++) acc[a][b][c] = 0.f;

    // ---------------- low-D (16) gram ----------------
    {
        uint32_t ea[4][4], eb[2][4];
        #pragma unroll
        for (int mi = 0; mi < 4; mi++) {
            int rE = rbaseA + mi * 16;
            ldsm4(ea[mi], sb + SM_EA + rE * 32 + (duA << 4));
        }
        #pragma unroll
        for (int nt = 0; nt < 2; nt++) {
            int nE = nbase + nt * 16;
            ldsm4(eb[nt], sb + SM_EB + nE * 32 + (duB << 4));
        }
        #pragma unroll
        for (int mi = 0; mi < 4; mi++)
            #pragma unroll
            for (int ni = 0; ni < 4; ni++)
                mma16816(acc[mi][ni], ea[mi], &eb[ni >> 1][(ni & 1) * 2]);
    }
    __half2 lhp[4][4][2];
    #pragma unroll
    for (int mi = 0; mi < 4; mi++) {
        int r0 = wr * 64 + mi * 16 + (lane >> 2), r1 = r0 + 8;
        float nl0 = nlI[r0], nl1 = nlI[r1];
        #pragma unroll
        for (int ni = 0; ni < 4; ni++) {
            int c0 = wc * 32 + ni * 8 + ((lane & 3) << 1), c1 = c0 + 1;
            float ol0 = nlJ[c0], ol1 = nlJ[c1];
            float l00 = sqrt_fast(fmaxf(fmaf(-2.f, acc[mi][ni][0], nl0 + ol0), 0.f));
            float l01 = sqrt_fast(fmaxf(fmaf(-2.f, acc[mi][ni][1], nl0 + ol1), 0.f));
            float l10 = sqrt_fast(fmaxf(fmaf(-2.f, acc[mi][ni][2], nl1 + ol0), 0.f));
            float l11 = sqrt_fast(fmaxf(fmaf(-2.f, acc[mi][ni][3], nl1 + ol1), 0.f));
            lhp[mi][ni][0] = __floats2half2_rn(l00, l01);
            lhp[mi][ni][1] = __floats2half2_rn(l10, l11);
            acc[mi][ni][0] = 0.f; acc[mi][ni][1] = 0.f;
            acc[mi][ni][2] = 0.f; acc[mi][ni][3] = 0.f;
        }
    }

    // ---------------- high-D mainloop: 7 chunks x 8 k-steps ----------------
    for (int c = 0; c < NCH; c++) {
        if (c > 0) __syncthreads();   // all warps done reading buffer (c+2)%3
        if (c + 2 < NCH) {
            int ss = (c + 2) % 3;
            const __half* pA = g_Xc + ((size_t)(c + 2) * Bn + i0) * 128;
            const __half* pB = g_Xc + ((size_t)(c + 2) * Bn + j0) * 128;
            uint32_t dA = sb + SM_STG + ss * 65536, dB = dA + 32768;
            #pragma unroll
            for (int p = 0; p < 8; p++) {
                int id = tid + p * 256;
                cpa16(dA + id * 16, pA + (size_t)id * 8);
                cpa16(dB + id * 16, pB + (size_t)id * 8);
            }
            asm volatile("cp.async.commit_group;" ::: "memory");
        }
        if (c < NCH - 1) {
            asm volatile("cp.async.wait_group 1;" ::: "memory");
        } else {
            asm volatile("cp.async.wait_group 0;" ::: "memory");
        }

        int s = c % 3;
        uint32_t bA = sb + SM_STG + s * 65536;
        uint32_t bB = bA + 32768;
        #pragma unroll
        for (int ks = 0; ks < 8; ks++) {
            uint32_t afr[4][4], bfr[2][4];
            #pragma unroll
            for (int mi = 0; mi < 4; mi++) {
                int row = rbaseA + mi * 16;
                ldsm4(afr[mi], bA + row * 256 + (((2 * ks + duA) ^ rmA) << 4));
            }
            #pragma unroll
            for (int nt = 0; nt < 2; nt++) {
                int nb = nbase + nt * 16;
                ldsm4(bfr[nt], bB + nb * 256 + (((2 * ks + duB) ^ rmB) << 4));
            }
            #pragma unroll
            for (int mi = 0; mi < 4; mi++)
                #pragma unroll
                for (int ni = 0; ni < 4; ni++)
                    mma16816(acc[mi][ni], afr[mi], &bfr[ni >> 1][(ni & 1) * 2]);
        }
    }

    // ---------------- epilogue: distances + moments ----------------
    float* rowSm = (float*)(smem + SM_ROW);
    float* colSm = (float*)(smem + SM_COL);
    float cacc[4][2][5];
    #pragma unroll
    for (int ni = 0; ni < 4; ni++)
        #pragma unroll
        for (int q = 0; q < 2; q++)
            #pragma unroll
            for (int m = 0; m < 5; m++) cacc[ni][q][m] = 0.f;

    #pragma unroll
    for (int mi = 0; mi < 4; mi++) {
        int r0 = wr * 64 + mi * 16 + (lane >> 2), r1 = r0 + 8;
        float nh0 = nhI[r0], nh1 = nhI[r1];
        float rA[5] = {0.f, 0.f, 0.f, 0.f, 0.f};
        float rB[5] = {0.f, 0.f, 0.f, 0.f, 0.f};
        #pragma unroll
        for (int ni = 0; ni < 4; ni++) {
            int c0 = wc * 32 + ni * 8 + ((lane & 3) << 1), c1 = c0 + 1;
            float oh0 = nhJ[c0], oh1 = nhJ[c1];
            float h00 = sqrt_fast(fmaxf(fmaf(-2.f, acc[mi][ni][0], nh0 + oh0), 0.f));
            float h01 = sqrt_fast(fmaxf(fmaf(-2.f, acc[mi][ni][1], nh0 + oh1), 0.f));
            float h10 = sqrt_fast(fmaxf(fmaf(-2.f, acc[mi][ni][2], nh1 + oh0), 0.f));
            float h11 = sqrt_fast(fmaxf(fmaf(-2.f, acc[mi][ni][3], nh1 + oh1), 0.f));
            float2 lp0 = __half22float2(lhp[mi][ni][0]);
            float2 lp1 = __half22float2(lhp[mi][ni][1]);
            rA[0] += h00 + h01;
            rA[1] += lp0.x + lp0.y;
            rA[2] = fmaf(h00, h00, fmaf(h01, h01, rA[2]));
            rA[3] = fmaf(lp0.x, lp0.x, fmaf(lp0.y, lp0.y, rA[3]));
            rA[4] = fmaf(h00, lp0.x, fmaf(h01, lp0.y, rA[4]));
            rB[0] += h10 + h11;
            rB[1] += lp1.x + lp1.y;
            rB[2] = fmaf(h10, h10, fmaf(h11, h11, rB[2]));
            rB[3] = fmaf(lp1.x, lp1.x, fmaf(lp1.y, lp1.y, rB[3]));
            rB[4] = fmaf(h10, lp1.x, fmaf(h11, lp1.y, rB[4]));
            cacc[ni][0][0] += h00 + h10;
            cacc[ni][0][1] += lp0.x + lp1.x;
            cacc[ni][0][2] = fmaf(h00, h00, fmaf(h10, h10, cacc[ni][0][2]));
            cacc[ni][0][3] = fmaf(lp0.x, lp0.x, fmaf(lp1.x, lp1.x, cacc[ni][0][3]));
            cacc[ni][0][4] = fmaf(h00, lp0.x, fmaf(h10, lp1.x, cacc[ni][0][4]));
            cacc[ni][1][0] += h01 + h11;
            cacc[ni][1][1] += lp0.y + lp1.y;
            cacc[ni][1][2] = fmaf(h01, h01, fmaf(h11, h11, cacc[ni][1][2]));
            cacc[ni][1][3] = fmaf(lp0.y, lp0.y, fmaf(lp1.y, lp1.y, cacc[ni][1][3]));
            cacc[ni][1][4] = fmaf(h01, lp0.y, fmaf(h11, lp1.y, cacc[ni][1][4]));
        }
        #pragma unroll
        for (int m = 0; m < 5; m++) {
            rA[m] += __shfl_xor_sync(0xffffffffu, rA[m], 1);
            rA[m] += __shfl_xor_sync(0xffffffffu, rA[m], 2);
            rB[m] += __shfl_xor_sync(0xffffffffu, rB[m], 1);
            rB[m] += __shfl_xor_sync(0xffffffffu, rB[m], 2);
        }
        if ((lane & 3) == 0) {
            #pragma unroll
            for (int m = 0; m < 5; m++) {
                rowSm[(wc * 128 + r0) * 5 + m] = rA[m];
                rowSm[(wc * 128 + r1) * 5 + m] = rB[m];
            }
        }
    }
    #pragma unroll
    for (int ni = 0; ni < 4; ni++)
        #pragma unroll
        for (int q = 0; q < 2; q++)
            #pragma unroll
            for (int m = 0; m < 5; m++) {
                float v = cacc[ni][q][m];
                v += __shfl_xor_sync(0xffffffffu, v, 4);
                v += __shfl_xor_sync(0xffffffffu, v, 8);
                v += __shfl_xor_sync(0xffffffffu, v, 16);
                cacc[ni][q][m] = v;
            }
    if (lane < 4) {
        #pragma unroll
        for (int ni = 0; ni < 4; ni++) {
            int c0 = wc * 32 + ni * 8 + (lane << 1);
            #pragma unroll
            for (int m = 0; m < 5; m++) {
                colSm[(wr * 128 + c0) * 5 + m]     = cacc[ni][0][m];
                colSm[(wr * 128 + c0 + 1) * 5 + m] = cacc[ni][1][m];
            }
        }
    }
    __syncthreads();

    if (tid < 128) {
        int r = tid;
        float s0 = 0.f, s1 = 0.f, s2 = 0.f, s3 = 0.f, s4 = 0.f;
        #pragma unroll
        for (int w = 0; w < 4; w++) {
            const float* p = &rowSm[(w * 128 + r) * 5];
            s0 += p[0]; s1 += p[1]; s2 += p[2]; s3 += p[3]; s4 += p[4];
        }
        int gi = i0 + r;
        atomicAdd(&g_Sh[gi],  (double)s0);
        atomicAdd(&g_Sl[gi],  (double)s1);
        atomicAdd(&g_Shh[gi], (double)s2);
        atomicAdd(&g_Sll[gi], (double)s3);
        atomicAdd(&g_Shl[gi], (double)s4);
    } else if (offdiag) {
        int cjj = tid - 128;
        float s0 = 0.f, s1 = 0.f, s2 = 0.f, s3 = 0.f, s4 = 0.f;
        #pragma unroll
        for (int w = 0; w < 2; w++) {
            const float* p = &colSm[(w * 128 + cjj) * 5];
            s0 += p[0]; s1 += p[1]; s2 += p[2]; s3 += p[3]; s4 += p[4];
        }
        int gj = j0 + cjj;
        atomicAdd(&g_Sh[gj],  (double)s0);
        atomicAdd(&g_Sl[gj],  (double)s1);
        atomicAdd(&g_Shh[gj], (double)s2);
        atomicAdd(&g_Sll[gj], (double)s3);
        atomicAdd(&g_Shl[gj], (double)s4);
    }
}

// ---------------------------------------------------------------------------
// Kernel 2: tail — per-row correlations + CE combine (1 block)
// ---------------------------------------------------------------------------
__global__ void __launch_bounds__(1024) tail_k(float* __restrict__ out) {
    int t = threadIdx.x;
    double corr = 0.0;
    const double invB = 1.0 / (double)Bn;
    for (int i = t; i < Bn; i += 1024) {
        double Sh = g_Sh[i], Sl = g_Sl[i];
        float num = (float)(g_Shl[i] - Sh * Sl * invB);
        float vh  = (float)fmax(g_Shh[i] - Sh * Sh * invB, 0.0);
        float vl  = (float)fmax(g_Sll[i] - Sl * Sl * invB, 0.0);
        corr += (double)(num * rsqrtf(fmaxf(vh, 1e-30f)) * rsqrtf(fmaxf(vl, 1e-30f)));
    }
    double ce = (t < NCEB) ? g_cePart[t] : 0.0;
    #pragma unroll
    for (int o = 16; o; o >>= 1) {
        corr += __shfl_xor_sync(0xffffffffu, corr, o);
        ce   += __shfl_xor_sync(0xffffffffu, ce, o);
    }
    __shared__ double rco[32], rce[32];
    if ((t & 31) == 0) { rco[t >> 5] = corr; rce[t >> 5] = ce; }
    __syncthreads();
    if (t == 0) {
        double sco = 0.0, sce = 0.0;
        #pragma unroll
        for (int w = 0; w < 32; w++) { sco += rco[w]; sce += rce[w]; }
        out[0] = (float)(ALPHA * (sce / (double)NTOT) - BETA * (sco / (double)Bn));
    }
}

// ---------------------------------------------------------------------------
extern "C" void kernel_launch(void* const* d_in, const int* in_sizes, int n_in,
                              void* d_out, int out_size) {
    (void)in_sizes; (void)n_in; (void)out_size;
    const float* E    = (const float*)d_in[0];
    const float* X    = (const float*)d_in[1];
    const int*   perm = (const int*)d_in[2];
    float* out = (float*)d_out;

    cudaFuncSetAttribute(pair_k, cudaFuncAttributeMaxDynamicSharedMemorySize, SM_TOT);

    prep_k<<<Bn + NCEB, 128>>>(X, E, perm);
    pair_k<<<NBLK, 256, SM_TOT>>>();
    tail_k<<<1, 1024>>>(out);
}